// round 16
// baseline (speedup 1.0000x reference)
#include <cuda_runtime.h>
#include <math.h>
#include <stdint.h>

// ---------------- problem constants ----------------
#define NL    4
#define DIM   384
#define HID   1536
#define NHD   6
#define HDM   64
#define NE    8
#define NTOP  2
#define SEQ   197
#define NB    8
#define NT    (NB*SEQ)     // 1576
#define NA    (NT*NTOP)    // 3152
#define NCLS  1000
#define NPAT  196
#define PFD   768
#define QKVD  (3*DIM)      // 1152
#define NOISE_N (NT*NE)
#define MOE2SK 4
#define QKVSK  2
#define PROJSK 4

// ---------------- scratch ----------------
__device__ __align__(16) float g_t[NT*DIM];
__device__ __align__(16) float g_th[NT*DIM];
__device__ __align__(16) float g_tl[NT*DIM];
__device__ __align__(16) float g_qp[QKVSK*NT*QKVD];
__device__ __align__(16) float g_o[NT*DIM];
__device__ __align__(16) float g_a[4*NT*DIM];
__device__ __align__(16) float g_patches[NB*NPAT*PFD];
__device__ float g_noise[NL*NOISE_N];
__device__ float g_logits[NT*NE];
__device__ int   g_ape[NA];
__device__ int   g_appos[NA];
__device__ float g_gates[NA];
__device__ int   g_cnt[NE];
__device__ int   g_off[NE+1];
__device__ int   g_list[NA];
__device__ int   g_posmap[NA];
__device__ __align__(16) float g_hh[NA*HID];
__device__ __align__(16) float g_hl[NA*HID];
__device__ __align__(16) float g_y[MOE2SK*NA*DIM];
__device__ float g_bias0[NL*NE*DIM];
__device__ float g_biassum[NTOP*DIM];
__device__ float g_cls[NB*DIM];

// ---------------- f32x2 packed helpers (scalar GEMM path) ----------------
__device__ __forceinline__ unsigned long long dup2(float b){
    unsigned long long r;
    asm("mov.b64 %0, {%1, %1};" : "=l"(r) : "r"(__float_as_uint(b)));
    return r;
}
__device__ __forceinline__ void ffma2(unsigned long long& acc,
                                      unsigned long long a, unsigned long long b){
    asm("fma.rn.f32x2 %0, %1, %2, %0;" : "+l"(acc) : "l"(a), "l"(b));
}
__device__ __forceinline__ float2 unpk(unsigned long long v){
    unsigned lo, hi;
    asm("mov.b64 {%0, %1}, %2;" : "=r"(lo), "=r"(hi) : "l"(v));
    return make_float2(__uint_as_float(lo), __uint_as_float(hi));
}

// ---------------- misc helpers ----------------
__device__ __forceinline__ float blk_sum(float v, float* s32){
    int lane = threadIdx.x & 31, w = threadIdx.x >> 5;
    #pragma unroll
    for (int o = 16; o; o >>= 1) v += __shfl_xor_sync(0xffffffffu, v, o);
    if (lane == 0) s32[w] = v;
    __syncthreads();
    int nw = blockDim.x >> 5;
    float r = (threadIdx.x < nw) ? s32[threadIdx.x] : 0.f;
    #pragma unroll
    for (int o = 16; o; o >>= 1) r += __shfl_xor_sync(0xffffffffu, r, o);
    if (threadIdx.x == 0) s32[0] = r;
    __syncthreads();
    r = s32[0];
    __syncthreads();
    return r;
}

__device__ __forceinline__ float gelu_exact(float v){
    return 0.5f * v * (1.0f + erff(v * 0.70710678118654752f));
}

__device__ __forceinline__ float2 tf32_pair(float a){
    uint32_t h;
    asm("cvt.rna.tf32.f32 %0, %1;" : "=r"(h) : "f"(a));
    float hf = __uint_as_float(h);
    float l = a - hf;
    uint32_t lb;
    asm("cvt.rna.tf32.f32 %0, %1;" : "=r"(lb) : "f"(l));
    return make_float2(hf, __uint_as_float(lb));
}

// ---------------- JAX threefry ----------------
__device__ __forceinline__ void threefry(unsigned k0, unsigned k1,
                                         unsigned& x0, unsigned& x1){
    unsigned ks2 = k0 ^ k1 ^ 0x1BD11BDAu;
    x0 += k0; x1 += k1;
#define TF_RND(r) { x0 += x1; x1 = (x1 << r) | (x1 >> (32 - r)); x1 ^= x0; }
    TF_RND(13) TF_RND(15) TF_RND(26) TF_RND(6)
    x0 += k1;  x1 += ks2 + 1u;
    TF_RND(17) TF_RND(29) TF_RND(16) TF_RND(24)
    x0 += ks2; x1 += k0 + 2u;
    TF_RND(13) TF_RND(15) TF_RND(26) TF_RND(6)
    x0 += k0;  x1 += k1 + 3u;
    TF_RND(17) TF_RND(29) TF_RND(16) TF_RND(24)
    x0 += k1;  x1 += ks2 + 4u;
    TF_RND(13) TF_RND(15) TF_RND(26) TF_RND(6)
    x0 += ks2; x1 += k0 + 5u;
#undef TF_RND
}

__device__ __forceinline__ float bits_to_normal(unsigned b){
    float f = __uint_as_float((b >> 9) | 0x3f800000u) - 1.0f;
    const float lo = -0.99999994f;
    float u = f * 2.0f + lo;
    u = fmaxf(lo, u);
    return 1.4142135623730951f * erfinvf(u);
}

__global__ void noise_k(){
    int l = blockIdx.y;
    int i = blockIdx.x * blockDim.x + threadIdx.x;
    if (i >= NOISE_N) return;
    unsigned kk0 = 0u, kk1 = (unsigned)l;
    threefry(0u, 42u, kk0, kk1);
    unsigned x0 = 0u, x1 = (unsigned)i;
    threefry(kk0, kk1, x0, x1);
    g_noise[l*NOISE_N + i] = bits_to_normal(x0 ^ x1);
}

// ---------------- patchify / assemble ----------------
__global__ void patchify_k(const float* __restrict__ x){
    int idx = blockIdx.x * blockDim.x + threadIdx.x;
    if (idx >= NB*NPAT*PFD) return;
    int f = idx % PFD;
    int r = idx / PFD;
    int n = r % NPAT;
    int b = r / NPAT;
    int c  = f >> 8;
    int rem = f & 255;
    int py = rem >> 4, px = rem & 15;
    int ph = n / 14, pw = n % 14;
    g_patches[idx] = x[ ((size_t)(b*3 + c)*224 + (ph*16 + py))*224 + (pw*16 + px) ];
}

__global__ void assemble_k(const float* __restrict__ cls, const float* __restrict__ pos){
    int idx = blockIdx.x * blockDim.x + threadIdx.x;
    if (idx >= NT*DIM) return;
    int d = idx % DIM;
    int ts = idx / DIM;
    int s = ts % SEQ, b = ts / SEQ;
    float v;
    if (s == 0) v = cls[d];
    else {
        size_t p = (size_t)(b*NPAT + (s-1))*DIM + d;
        const size_t st = (size_t)NB*NPAT*DIM;
        v = g_a[p] + g_a[st + p] + g_a[2*st + p] + g_a[3*st + p];
    }
    float y = v + pos[s*DIM + d];
    g_t[idx] = y;
    float2 pr = tf32_pair(y);
    g_th[idx] = pr.x;
    g_tl[idx] = pr.y;
}

// =================== scalar f32x2 64x64 split-K GEMM (patch) ===============
#define GEMM2(BM, R, LH, A_LOAD_EXPR, KDIM)                                   \
    __shared__ float As[2][16][(BM)+4];                                       \
    __shared__ float Bs[2][16][68];                                           \
    int tx = tid & 15, ty = tid >> 4;                                         \
    int am = tid >> 2, ak = (tid & 3) << 2;                                   \
    int bk = tid >> 4, bn = (tid & 15) << 2;                                  \
    unsigned long long acc2[(R)/2][4];                                        \
    _Pragma("unroll") for (int i = 0; i < (R)/2; i++)                         \
      _Pragma("unroll") for (int j = 0; j < 4; j++) acc2[i][j] = 0ull;        \
    float4 ra[LH], rb;                                                        \
    {   int k0 = 0;                                                           \
        _Pragma("unroll") for (int hh = 0; hh < (LH); hh++){                  \
            int m = am + hh*64; ra[hh] = A_LOAD_EXPR; }                       \
        rb = *(const float4*)&Bp[(size_t)bk*Nn + n0 + bn];                    \
    }                                                                         \
    _Pragma("unroll") for (int hh = 0; hh < (LH); hh++){                      \
        int m = am + hh*64;                                                   \
        As[0][ak+0][m]=ra[hh].x; As[0][ak+1][m]=ra[hh].y;                     \
        As[0][ak+2][m]=ra[hh].z; As[0][ak+3][m]=ra[hh].w; }                   \
    *(float4*)&Bs[0][bk][bn] = rb;                                            \
    __syncthreads();                                                          \
    const int nk = (KDIM)/16;                                                 \
    for (int kt = 0; kt < nk; kt++){                                          \
        int cur = kt & 1;                                                     \
        if (kt+1 < nk){                                                       \
            int k0 = (kt+1)*16;                                               \
            _Pragma("unroll") for (int hh = 0; hh < (LH); hh++){              \
                int m = am + hh*64; ra[hh] = A_LOAD_EXPR; }                   \
            rb = *(const float4*)&Bp[(size_t)(k0+bk)*Nn + n0 + bn];           \
        }                                                                     \
        _Pragma("unroll")                                                     \
        for (int kk = 0; kk < 16; kk++){                                      \
            float4 bv = *(float4*)&Bs[cur][kk][tx*4];                         \
            unsigned long long bd0=dup2(bv.x), bd1=dup2(bv.y),                \
                               bd2=dup2(bv.z), bd3=dup2(bv.w);                \
            _Pragma("unroll")                                                 \
            for (int ii = 0; ii < (R)/4; ii++){                               \
                ulonglong2 aa = *(const ulonglong2*)&As[cur][kk][ty*(R)+ii*4];\
                ffma2(acc2[ii*2+0][0], aa.x, bd0);                            \
                ffma2(acc2[ii*2+0][1], aa.x, bd1);                            \
                ffma2(acc2[ii*2+0][2], aa.x, bd2);                            \
                ffma2(acc2[ii*2+0][3], aa.x, bd3);                            \
                ffma2(acc2[ii*2+1][0], aa.y, bd0);                            \
                ffma2(acc2[ii*2+1][1], aa.y, bd1);                            \
                ffma2(acc2[ii*2+1][2], aa.y, bd2);                            \
                ffma2(acc2[ii*2+1][3], aa.y, bd3);                            \
            }                                                                 \
        }                                                                     \
        if (kt+1 < nk){                                                       \
            int nxt = 1 - cur;                                                \
            _Pragma("unroll") for (int hh = 0; hh < (LH); hh++){              \
                int m = am + hh*64;                                           \
                As[nxt][ak+0][m]=ra[hh].x; As[nxt][ak+1][m]=ra[hh].y;         \
                As[nxt][ak+2][m]=ra[hh].z; As[nxt][ak+3][m]=ra[hh].w; }       \
            *(float4*)&Bs[nxt][bk][bn] = rb;                                  \
        }                                                                     \
        __syncthreads();                                                      \
    }

__global__ void __launch_bounds__(256, 2)
sgemm64sk(const float* __restrict__ A, const float* __restrict__ Bp0,
          const float* __restrict__ bias, float* __restrict__ C,
          int M, int Nn, int K, int Kh){
    int tid = threadIdx.x;
    int z = blockIdx.z;
    int koff = z * Kh;
    const float* Bp = Bp0 + (size_t)koff * Nn;
    int m0 = blockIdx.x * 64, n0 = blockIdx.y * 64;
    GEMM2(64, 4, 1,
          (m0+m < M) ? *(const float4*)&A[(size_t)(m0+m)*K + koff + k0 + ak]
                     : make_float4(0,0,0,0), Kh)
    float4 bb = make_float4(0,0,0,0);
    if (z == 0) bb = *(const float4*)&bias[n0 + tx*4];
    float* Cz = C + (size_t)z*M*Nn;
    #pragma unroll
    for (int i2 = 0; i2 < 2; i2++){
        float2 u0=unpk(acc2[i2][0]), u1=unpk(acc2[i2][1]),
               u2=unpk(acc2[i2][2]), u3=unpk(acc2[i2][3]);
        int r = m0 + ty*4 + i2*2;
        if (r < M)
            *(float4*)&Cz[(size_t)r*Nn + n0 + tx*4] =
                make_float4(u0.x+bb.x, u1.x+bb.y, u2.x+bb.z, u3.x+bb.w);
        if (r+1 < M)
            *(float4*)&Cz[(size_t)(r+1)*Nn + n0 + tx*4] =
                make_float4(u0.y+bb.x, u1.y+bb.y, u2.y+bb.z, u3.y+bb.w);
    }
}

// =================== mma.sync TF32 (3xTF32) GEMM ===========================
#define MMA_SMEM ((2*8448 + 128)*4)

#define SA_H(b,k,m) sm[(b)*8448 + (k)*132 + (m)]
#define SA_L(b,k,m) sm[(b)*8448 + 2112 + (k)*132 + (m)]
#define SB_H(b,k,n) sm[(b)*8448 + 4224 + (k)*132 + (n)]
#define SB_L(b,k,n) sm[(b)*8448 + 6336 + (k)*132 + (n)]

#define MMA8(c, a, b)                                                         \
    asm volatile("mma.sync.aligned.m16n8k8.row.col.f32.tf32.tf32.f32 "        \
        "{%0,%1,%2,%3}, {%4,%5,%6,%7}, {%8,%9}, {%0,%1,%2,%3};"               \
        : "+f"((c)[0]), "+f"((c)[1]), "+f"((c)[2]), "+f"((c)[3])              \
        : "r"(__float_as_uint((a)[0])), "r"(__float_as_uint((a)[1])),         \
          "r"(__float_as_uint((a)[2])), "r"(__float_as_uint((a)[3])),         \
          "r"(__float_as_uint((b)[0])), "r"(__float_as_uint((b)[1])))

// staging when A arrives pre-split
#define STAGE_STORE(b)                                                        \
    _Pragma("unroll") for (int i = 0; i < 2; i++){                            \
        int idx = tid + i*256; int m = idx >> 2; int kq = (idx & 3) << 2;     \
        SA_H(b,kq+0,m)=rah[i].x; SA_L(b,kq+0,m)=ral[i].x;                     \
        SA_H(b,kq+1,m)=rah[i].y; SA_L(b,kq+1,m)=ral[i].y;                     \
        SA_H(b,kq+2,m)=rah[i].z; SA_L(b,kq+2,m)=ral[i].z;                     \
        SA_H(b,kq+3,m)=rah[i].w; SA_L(b,kq+3,m)=ral[i].w;                     \
    }                                                                         \
    _Pragma("unroll") for (int i = 0; i < 2; i++){                            \
        int idx = tid + i*256; int r = idx >> 5; int c = (idx & 31) << 2;     \
        float2 q0 = tf32_pair(rbr[i].x), q1 = tf32_pair(rbr[i].y);            \
        float2 q2 = tf32_pair(rbr[i].z), q3 = tf32_pair(rbr[i].w);            \
        *(float4*)&SB_H(b,r,c) = make_float4(q0.x,q1.x,q2.x,q3.x);            \
        *(float4*)&SB_L(b,r,c) = make_float4(q0.y,q1.y,q2.y,q3.y);            \
    }

// staging when A arrives raw (split here)
#define STAGE_STORE_RAW(b)                                                    \
    _Pragma("unroll") for (int i = 0; i < 2; i++){                            \
        int idx = tid + i*256; int m = idx >> 2; int kq = (idx & 3) << 2;     \
        float2 p0 = tf32_pair(rah[i].x), p1 = tf32_pair(rah[i].y);            \
        float2 p2 = tf32_pair(rah[i].z), p3 = tf32_pair(rah[i].w);            \
        SA_H(b,kq+0,m)=p0.x; SA_L(b,kq+0,m)=p0.y;                             \
        SA_H(b,kq+1,m)=p1.x; SA_L(b,kq+1,m)=p1.y;                             \
        SA_H(b,kq+2,m)=p2.x; SA_L(b,kq+2,m)=p2.y;                             \
        SA_H(b,kq+3,m)=p3.x; SA_L(b,kq+3,m)=p3.y;                             \
    }                                                                         \
    _Pragma("unroll") for (int i = 0; i < 2; i++){                            \
        int idx = tid + i*256; int r = idx >> 5; int c = (idx & 31) << 2;     \
        float2 q0 = tf32_pair(rbr[i].x), q1 = tf32_pair(rbr[i].y);            \
        float2 q2 = tf32_pair(rbr[i].z), q3 = tf32_pair(rbr[i].w);            \
        *(float4*)&SB_H(b,r,c) = make_float4(q0.x,q1.x,q2.x,q3.x);            \
        *(float4*)&SB_L(b,r,c) = make_float4(q0.y,q1.y,q2.y,q3.y);            \
    }

#define TF32_MAINLOOP(KDIM, PRELOAD, STAGE)                                   \
    STAGE(0)                                                                  \
    __syncthreads();                                                          \
    const int nk = (KDIM)/16;                                                 \
    for (int kt = 0; kt < nk; kt++){                                          \
        int cur = kt & 1;                                                     \
        if (kt+1 < nk){ int k0n = (kt+1)*16; PRELOAD }                        \
        _Pragma("unroll") for (int ks = 0; ks < 2; ks++){                     \
            float ah[4][4], al[4][4];                                         \
            _Pragma("unroll") for (int mt = 0; mt < 4; mt++){                 \
                int mi = warp_m*64 + mt*16 + g;                               \
                int kr = ks*8 + tig;                                          \
                ah[mt][0]=SA_H(cur,kr,mi);   ah[mt][1]=SA_H(cur,kr,mi+8);     \
                ah[mt][2]=SA_H(cur,kr+4,mi); ah[mt][3]=SA_H(cur,kr+4,mi+8);   \
                al[mt][0]=SA_L(cur,kr,mi);   al[mt][1]=SA_L(cur,kr,mi+8);     \
                al[mt][2]=SA_L(cur,kr+4,mi); al[mt][3]=SA_L(cur,kr+4,mi+8);   \
            }                                                                 \
            float bhf[4][2], blf[4][2];                                       \
            _Pragma("unroll") for (int nt = 0; nt < 4; nt++){                 \
                int ni = warp_n*32 + nt*8 + g;                                \
                int kr = ks*8 + tig;                                          \
                bhf[nt][0]=SB_H(cur,kr,ni); bhf[nt][1]=SB_H(cur,kr+4,ni);     \
                blf[nt][0]=SB_L(cur,kr,ni); blf[nt][1]=SB_L(cur,kr+4,ni);     \
            }                                                                 \
            _Pragma("unroll") for (int mt = 0; mt < 4; mt++)                  \
                _Pragma("unroll") for (int nt = 0; nt < 4; nt++){             \
                    MMA8(acc[mt][nt], ah[mt], bhf[nt]);                       \
                    MMA8(acc[mt][nt], ah[mt], blf[nt]);                       \
                    MMA8(acc[mt][nt], al[mt], bhf[nt]);                       \
                }                                                             \
        }                                                                     \
        if (kt+1 < nk){ int nxt = 1 - cur; STAGE(nxt) }                       \
        __syncthreads();                                                      \
    }

#define TF32_HEAD                                                             \
    const int lane = tid & 31;                                                \
    const int warp_m = (tid >> 5) & 1, warp_n = tid >> 6;                     \
    const int g = lane >> 2, tig = lane & 3;                                  \
    float acc[4][4][4];                                                       \
    _Pragma("unroll") for (int i = 0; i < 4; i++)                             \
      _Pragma("unroll") for (int j = 0; j < 4; j++)                           \
        _Pragma("unroll") for (int q = 0; q < 4; q++) acc[i][j][q] = 0.f;

#define TF32_CORE(KDIM, A4H, A4L, B4)                                         \
    TF32_HEAD                                                                 \
    float4 rah[2], ral[2], rbr[2];                                            \
    {                                                                         \
        _Pragma("unroll") for (int i = 0; i < 2; i++){                        \
            int idx = tid + i*256; int m = idx >> 2;                          \
            int kq = (idx & 3) << 2;                                          \
            rah[i] = A4H; ral[i] = A4L; }                                     \
        _Pragma("unroll") for (int i = 0; i < 2; i++){                        \
            int idx = tid + i*256; int r = idx >> 5;                          \
            int c = (idx & 31) << 2;                                          \
            rbr[i] = B4; }                                                    \
    }                                                                         \
    TF32_MAINLOOP(KDIM,                                                       \
        _Pragma("unroll") for (int i = 0; i < 2; i++){                        \
            int idx = tid + i*256; int m = idx >> 2;                          \
            int kq = ((idx & 3) << 2) + k0n;                                  \
            rah[i] = A4H; ral[i] = A4L; }                                     \
        _Pragma("unroll") for (int i = 0; i < 2; i++){                        \
            int idx = tid + i*256; int r = (idx >> 5) + k0n;                  \
            int c = (idx & 31) << 2;                                          \
            rbr[i] = B4; } ,                                                  \
        STAGE_STORE)

#define TF32_CORE_RAW(KDIM, A4, B4)                                           \
    TF32_HEAD                                                                 \
    float4 rah[2], rbr[2];                                                    \
    {                                                                         \
        _Pragma("unroll") for (int i = 0; i < 2; i++){                        \
            int idx = tid + i*256; int m = idx >> 2;                          \
            int kq = (idx & 3) << 2;                                          \
            rah[i] = A4; }                                                    \
        _Pragma("unroll") for (int i = 0; i < 2; i++){                        \
            int idx = tid + i*256; int r = idx >> 5;                          \
            int c = (idx & 31) << 2;                                          \
            rbr[i] = B4; }                                                    \
    }                                                                         \
    TF32_MAINLOOP(KDIM,                                                       \
        _Pragma("unroll") for (int i = 0; i < 2; i++){                        \
            int idx = tid + i*256; int m = idx >> 2;                          \
            int kq = ((idx & 3) << 2) + k0n;                                  \
            rah[i] = A4; }                                                    \
        _Pragma("unroll") for (int i = 0; i < 2; i++){                        \
            int idx = tid + i*256; int r = (idx >> 5) + k0n;                  \
            int c = (idx & 31) << 2;                                          \
            rbr[i] = B4; } ,                                                  \
        STAGE_STORE_RAW)

// ---- MoE FFN1 ----
__global__ void __launch_bounds__(256)
moe1_mma(const float* __restrict__ w1, const float* __restrict__ b1){
    int e = blockIdx.z;
    int cnt = g_cnt[e];
    int m0 = blockIdx.x * 128;
    if (m0 >= cnt) return;
    int off = g_off[e];
    extern __shared__ float sm[];
    int* rows = (int*)(sm + 2*8448);
    int tid = threadIdx.x;
    if (tid < 128) rows[tid] = (m0 + tid < cnt) ? (g_list[off + m0 + tid] >> 1) : 0;
    __syncthreads();
    int n0 = blockIdx.y * 128;
    const float* Bw = w1 + (size_t)e*DIM*HID;
    TF32_CORE(DIM,
        (*(const float4*)&g_th[(size_t)rows[m]*DIM + kq]),
        (*(const float4*)&g_tl[(size_t)rows[m]*DIM + kq]),
        (*(const float4*)&Bw[(size_t)r*HID + n0 + c]))
    #pragma unroll
    for (int mt = 0; mt < 4; mt++){
        #pragma unroll
        for (int nt = 0; nt < 4; nt++){
            int lr = warp_m*64 + mt*16 + g;
            int col = n0 + warp_n*32 + nt*8 + tig*2;
            float b0v = b1[e*HID + col], b1v = b1[e*HID + col + 1];
            int r1 = m0 + lr;
            if (r1 < cnt){
                float v0 = gelu_exact(acc[mt][nt][0]+b0v);
                float v1 = gelu_exact(acc[mt][nt][1]+b1v);
                float2 s0 = tf32_pair(v0), s1 = tf32_pair(v1);
                size_t p = (size_t)(off+r1)*HID + col;
                *(float2*)&g_hh[p] = make_float2(s0.x, s1.x);
                *(float2*)&g_hl[p] = make_float2(s0.y, s1.y);
            }
            int r2 = r1 + 8;
            if (r2 < cnt){
                float v0 = gelu_exact(acc[mt][nt][2]+b0v);
                float v1 = gelu_exact(acc[mt][nt][3]+b1v);
                float2 s0 = tf32_pair(v0), s1 = tf32_pair(v1);
                size_t p = (size_t)(off+r2)*HID + col;
                *(float2*)&g_hh[p] = make_float2(s0.x, s1.x);
                *(float2*)&g_hl[p] = make_float2(s0.y, s1.y);
            }
        }
    }
}

// ---- MoE FFN2 (split-K=MOE2SK) ----
__global__ void __launch_bounds__(256)
moe2_mma(const float* __restrict__ w2, const float* __restrict__ b2){
    int ez = blockIdx.z;
    int e = ez / MOE2SK, zk = ez % MOE2SK;
    int cnt = g_cnt[e];
    int m0 = blockIdx.x * 128;
    if (m0 >= cnt) return;
    int off = g_off[e];
    extern __shared__ float sm[];
    int tid = threadIdx.x;
    int n0 = blockIdx.y * 128;
    const int KH = HID / MOE2SK;
    int koff = zk * KH;
    const float* Bw = w2 + (size_t)e*HID*DIM;
    TF32_CORE(KH,
        (*(const float4*)&g_hh[(size_t)(off + ((m0+m < cnt) ? (m0+m) : (cnt-1)))*HID + koff + kq]),
        (*(const float4*)&g_hl[(size_t)(off + ((m0+m < cnt) ? (m0+m) : (cnt-1)))*HID + koff + kq]),
        (*(const float4*)&Bw[(size_t)(koff + r)*DIM + n0 + c]))
    float* Y = g_y + (size_t)zk*NA*DIM;
    #pragma unroll
    for (int mt = 0; mt < 4; mt++){
        #pragma unroll
        for (int nt = 0; nt < 4; nt++){
            int lr = warp_m*64 + mt*16 + g;
            int col = n0 + warp_n*32 + nt*8 + tig*2;
            float b0v = 0.f, b1v = 0.f;
            if (zk == 0){ b0v = b2[e*DIM + col]; b1v = b2[e*DIM + col + 1]; }
            int r1 = m0 + lr;
            if (r1 < cnt)
                *(float2*)&Y[(size_t)(off+r1)*DIM + col] =
                    make_float2(acc[mt][nt][0]+b0v, acc[mt][nt][1]+b1v);
            int r2 = r1 + 8;
            if (r2 < cnt)
                *(float2*)&Y[(size_t)(off+r2)*DIM + col] =
                    make_float2(acc[mt][nt][2]+b0v, acc[mt][nt][3]+b1v);
        }
    }
}

// ---- QKV (split-K=QKVSK; partials consumed directly by attention) ----
__global__ void __launch_bounds__(256)
qkv_mma(const float* __restrict__ wq, const float* __restrict__ bq){
    int m0 = blockIdx.x * 128;
    int zk = blockIdx.z;
    extern __shared__ float sm[];
    int tid = threadIdx.x;
    int n0 = blockIdx.y * 128;
    const int KH = DIM / QKVSK;
    int koff = zk * KH;
    TF32_CORE(KH,
        (*(const float4*)&g_th[(size_t)((m0+m < NT) ? (m0+m) : (NT-1))*DIM + koff + kq]),
        (*(const float4*)&g_tl[(size_t)((m0+m < NT) ? (m0+m) : (NT-1))*DIM + koff + kq]),
        (*(const float4*)&wq[(size_t)(koff + r)*QKVD + n0 + c]))
    float* P = g_qp + (size_t)zk*NT*QKVD;
    #pragma unroll
    for (int mt = 0; mt < 4; mt++){
        #pragma unroll
        for (int nt = 0; nt < 4; nt++){
            int lr = warp_m*64 + mt*16 + g;
            int col = n0 + warp_n*32 + nt*8 + tig*2;
            float b0v = 0.f, b1v = 0.f;
            if (zk == 0){ b0v = bq[col]; b1v = bq[col + 1]; }
            int r1 = m0 + lr;
            if (r1 < NT)
                *(float2*)&P[(size_t)r1*QKVD + col] =
                    make_float2(acc[mt][nt][0]+b0v, acc[mt][nt][1]+b1v);
            int r2 = r1 + 8;
            if (r2 < NT)
                *(float2*)&P[(size_t)r2*QKVD + col] =
                    make_float2(acc[mt][nt][2]+b0v, acc[mt][nt][3]+b1v);
        }
    }
}

// ---- attn proj (split-K=PROJSK; raw A from g_o, split at staging) ----
__global__ void __launch_bounds__(256)
proj_mma(const float* __restrict__ wp, const float* __restrict__ bp){
    int m0 = blockIdx.x * 128;
    int zk = blockIdx.z;
    extern __shared__ float sm[];
    int tid = threadIdx.x;
    int n0 = blockIdx.y * 128;
    const int KH = DIM / PROJSK;   // 96
    int koff = zk * KH;
    TF32_CORE_RAW(KH,
        (*(const float4*)&g_o[(size_t)((m0+m < NT) ? (m0+m) : (NT-1))*DIM + koff + kq]),
        (*(const float4*)&wp[(size_t)(koff + r)*DIM + n0 + c]))
    float* P = g_a + (size_t)zk*NT*DIM;
    #pragma unroll
    for (int mt = 0; mt < 4; mt++){
        #pragma unroll
        for (int nt = 0; nt < 4; nt++){
            int lr = warp_m*64 + mt*16 + g;
            int col = n0 + warp_n*32 + nt*8 + tig*2;
            float b0v = 0.f, b1v = 0.f;
            if (zk == 0){ b0v = bp[col]; b1v = bp[col + 1]; }
            int r1 = m0 + lr;
            if (r1 < NT)
                *(float2*)&P[(size_t)r1*DIM + col] =
                    make_float2(acc[mt][nt][0]+b0v, acc[mt][nt][1]+b1v);
            int r2 = r1 + 8;
            if (r2 < NT)
                *(float2*)&P[(size_t)r2*DIM + col] =
                    make_float2(acc[mt][nt][2]+b0v, acc[mt][nt][3]+b1v);
        }
    }
}

// ---------------- fused attention (sums qkv split-K partials inline) -------
__global__ void attn_fused_k(){
    int bh = blockIdx.y; int b = bh / NHD, h = bh % NHD;
    int q0 = blockIdx.x * 32;
    __shared__ float Qs[32][68];
    __shared__ float KVs[32][68];
    __shared__ float Ss[32][224];
    int tid = threadIdx.x;
    const size_t qst = (size_t)NT*QKVD;
    #pragma unroll
    for (int li = 0; li < 2; li++){
        int idx = tid + li*256;
        int r = idx >> 4, c = (idx & 15) << 2;
        int q = q0 + r;
        float4 v = make_float4(0,0,0,0);
        if (q < SEQ){
            size_t p = (size_t)(b*SEQ+q)*QKVD + h*HDM + c;
            float4 v0 = *(const float4*)&g_qp[p];
            float4 v1 = *(const float4*)&g_qp[qst + p];
            v = make_float4(v0.x+v1.x, v0.y+v1.y, v0.z+v1.z, v0.w+v1.w);
        }
        *(float4*)&Qs[r][c] = v;
    }
    int tx = tid & 15, ty = tid >> 4;
    for (int k0 = 0; k0 < 224; k0 += 32){
        #pragma unroll
        for (int li = 0; li < 2; li++){
            int idx = tid + li*256;
            int r = idx >> 4, c = (idx & 15) << 2;
            int k = k0 + r;
            float4 w = make_float4(0,0,0,0);
            if (k < SEQ){
                size_t p = (size_t)(b*SEQ+k)*QKVD + DIM + h*HDM + c;
                float4 v0 = *(const float4*)&g_qp[p];
                float4 v1 = *(const float4*)&g_qp[qst + p];
                w = make_float4(v0.x+v1.x, v0.y+v1.y, v0.z+v1.z, v0.w+v1.w);
            }
            *(float4*)&KVs[r][c] = w;
        }
        __syncthreads();
        float acc[2][2] = {};
        #pragma unroll
        for (int d = 0; d < HDM; d++){
            float a0 = Qs[ty*2][d],   a1 = Qs[ty*2+1][d];
            float b0 = KVs[tx*2][d],  b1 = KVs[tx*2+1][d];
            acc[0][0] += a0*b0; acc[0][1] += a0*b1;
            acc[1][0] += a1*b0; acc[1][1] += a1*b1;
        }
        #pragma unroll
        for (int i = 0; i < 2; i++){
            #pragma unroll
            for (int j = 0; j < 2; j++){
                int k = k0 + tx*2 + j;
                Ss[ty*2+i][k] = (k < SEQ) ? acc[i][j]*0.125f : -1.0e30f;
            }
        }
        __syncthreads();
    }
    int lane = tid & 31, w = tid >> 5;
    #pragma unroll
    for (int rr = 0; rr < 4; rr++){
        int row = w*4 + rr;
        float m = -3.0e38f;
        for (int i = lane; i < SEQ; i += 32) m = fmaxf(m, Ss[row][i]);
        #pragma unroll
        for (int o = 16; o; o >>= 1) m = fmaxf(m, __shfl_xor_sync(0xffffffffu, m, o));
        float s = 0.f;
        for (int i = lane; i < SEQ; i += 32){
            float e = expf(Ss[row][i] - m);
            Ss[row][i] = e; s += e;
        }
        #pragma unroll
        for (int o = 16; o; o >>= 1) s += __shfl_xor_sync(0xffffffffu, s, o);
        float inv = 1.0f / s;
        for (int i = lane; i < 224; i += 32)
            Ss[row][i] = (i < SEQ) ? Ss[row][i]*inv : 0.f;
    }
    __syncthreads();
    // AV: each thread owns rows (vr + 8i, i<4) x cols (vc, vc+1)
    int vc = (tid & 31) << 1;
    int vr = tid >> 5;
    float accv[4][2] = {};
    for (int k0 = 0; k0 < 224; k0 += 32){
        #pragma unroll
        for (int li = 0; li < 2; li++){
            int idx = tid + li*256;
            int r = idx >> 4, c = (idx & 15) << 2;
            int k = k0 + r;
            float4 v = make_float4(0,0,0,0);
            if (k < SEQ){
                size_t p = (size_t)(b*SEQ+k)*QKVD + 2*DIM + h*HDM + c;
                float4 v0 = *(const float4*)&g_qp[p];
                float4 v1 = *(const float4*)&g_qp[qst + p];
                v = make_float4(v0.x+v1.x, v0.y+v1.y, v0.z+v1.z, v0.w+v1.w);
            }
            *(float4*)&KVs[r][c] = v;
        }
        __syncthreads();
        #pragma unroll
        for (int kk = 0; kk < 32; kk++){
            float2 vv = *(float2*)&KVs[kk][vc];
            #pragma unroll
            for (int i = 0; i < 4; i++){
                float s = Ss[vr + 8*i][k0+kk];
                accv[i][0] += s*vv.x;
                accv[i][1] += s*vv.y;
            }
        }
        __syncthreads();
    }
    #pragma unroll
    for (int i = 0; i < 4; i++){
        int q = q0 + vr + 8*i;
        if (q < SEQ)
            *(float2*)&g_o[(size_t)(b*SEQ+q)*DIM + h*HDM + vc] =
                make_float2(accv[i][0], accv[i][1]);
    }
}

// ---------------- fused: residual add + LN1 + router (+ split emit) --------
__global__ void add_ln_router_k(const float* __restrict__ gw, const float* __restrict__ bw,
                                const float* __restrict__ rw, const float* __restrict__ rb,
                                const float* __restrict__ noise){
    int t = blockIdx.x;
    __shared__ float buf[DIM];
    __shared__ float red[32];
    __shared__ float s_part[4][NE];
    int tid = threadIdx.x;
    float s = 0.f;
    const size_t st = (size_t)NT*DIM;
    #pragma unroll
    for (int j = 0; j < 3; j++){
        int i = tid + 128*j;
        size_t p = (size_t)t*DIM + i;
        float v = g_t[p] + g_a[p] + g_a[st + p] + g_a[2*st + p] + g_a[3*st + p];
        buf[i] = v; s += v;
    }
    float mean = blk_sum(s, red) * (1.0f/DIM);
    float vs = 0.f;
    #pragma unroll
    for (int j = 0; j < 3; j++){ float d = buf[tid+128*j] - mean; vs += d*d; }
    float var = blk_sum(vs, red) * (1.0f/DIM);
    float inv = rsqrtf(var + 1e-5f);
    float acc[NE] = {};
    #pragma unroll
    for (int j = 0; j < 3; j++){
        int i = tid + 128*j;
        float y = (buf[i] - mean) * inv * gw[i] + bw[i];
        g_t[(size_t)t*DIM + i] = y;
        float2 pr = tf32_pair(y);
        g_th[(size_t)t*DIM + i] = pr.x;
        g_tl[(size_t)t*DIM + i] = pr.y;
        float4 r0 = *(const float4*)&rw[i*NE];
        float4 r1 = *(const float4*)&rw[i*NE + 4];
        acc[0] += y*r0.x; acc[1] += y*r0.y; acc[2] += y*r0.z; acc[3] += y*r0.w;
        acc[4] += y*r1.x; acc[5] += y*r1.y; acc[6] += y*r1.z; acc[7] += y*r1.w;
    }
    int lane = tid & 31, w = tid >> 5;
    #pragma unroll
    for (int e = 0; e < NE; e++){
        float v = acc[e];
        #pragma unroll
        for (int o = 16; o; o >>= 1) v += __shfl_xor_sync(0xffffffffu, v, o);
        if (lane == 0) s_part[w][e] = v;
    }
    __syncthreads();
    if (tid < NE){
        float v = s_part[0][tid] + s_part[1][tid] + s_part[2][tid] + s_part[3][tid];
        g_logits[t*NE + tid] = v + rb[tid] + 0.01f * noise[t*NE + tid];
    }
}

// ---------------- routing ----------------
__global__ void route_k(const float* __restrict__ bias0){
    __shared__ int s_cnt[NE];
    __shared__ int s_off[NE];
    __shared__ int s_occ[NTOP*NE];
    int tid = threadIdx.x;
    if (tid < NE) s_cnt[tid] = 0;
    if (tid < NTOP*NE) s_occ[tid] = 0;
    __syncthreads();
    for (int t = tid; t < NT; t += 1024){
        float v[NE];
        #pragma unroll
        for (int e = 0; e < NE; e++) v[e] = g_logits[t*NE + e];
        int i0 = 0; float v0 = v[0];
        #pragma unroll
        for (int e = 1; e < NE; e++) if (v[e] > v0){ v0 = v[e]; i0 = e; }
        int i1 = (i0 == 0) ? 1 : 0; float v1 = v[i1];
        #pragma unroll
        for (int e = 0; e < NE; e++) if (e != i0 && v[e] > v1){ v1 = v[e]; i1 = e; }
        float e1 = expf(v1 - v0);
        float inv = 1.0f / (1.0f + e1);
        g_gates[t*2]   = inv;
        g_gates[t*2+1] = e1 * inv;
        g_ape[t*2]   = i0;
        g_ape[t*2+1] = i1;
        g_appos[t*2]   = atomicAdd(&s_cnt[i0], 1);
        g_appos[t*2+1] = atomicAdd(&s_cnt[i1], 1);
        s_occ[i0] = 1;
        s_occ[NE + i1] = 1;
    }
    __syncthreads();
    if (tid == 0){
        int o = 0;
        for (int e = 0; e < NE; e++){
            s_off[e] = o; g_off[e] = o; g_cnt[e] = s_cnt[e]; o += s_cnt[e];
        }
        g_off[NE] = o;
    }
    __syncthreads();
    for (int j = tid; j < NA; j += 1024){
        int e = g_ape[j];
        int pos = s_off[e] + g_appos[j];
        g_list[pos] = j;
        g_posmap[j] = pos;
    }
    if (tid < NTOP*DIM){
        int k = tid / DIM, d = tid % DIM;
        float s = 0.f;
        #pragma unroll
        for (int e = 0; e < NE; e++)
            if (s_occ[k*NE + e]) s += bias0[e*DIM + d];
        g_biassum[k*DIM + d] = s;
    }
}

__global__ void bias0_all_k(const float* __restrict__ b1, const float* __restrict__ w2,
                            const float* __restrict__ b2){
    int l = blockIdx.z;
    int e = blockIdx.x;
    __shared__ float gb[HID];
    int tid = threadIdx.x;
    const float* b1l = b1 + ((size_t)l*NE + e)*HID;
    for (int h = tid; h < HID; h += 128) gb[h] = gelu_exact(b1l[h]);
    __syncthreads();
    int d = blockIdx.y * 128 + tid;
    const float* w = w2 + ((size_t)l*NE + e)*HID*DIM + d;
    float acc = b2[((size_t)l*NE + e)*DIM + d];
    for (int h = 0; h < HID; h++)
        acc += gb[h] * w[(size_t)h*DIM];
    g_bias0[((size_t)l*NE + e)*DIM + d] = acc;
}

// ---------------- fused: MoE combine (partials) + residual + LN2 -----------
__global__ void combine_ln_k(const float* __restrict__ bias0,
                             const float* __restrict__ gw, const float* __restrict__ bw){
    int t = blockIdx.x;
    __shared__ float buf[DIM];
    __shared__ float red[32];
    int tid = threadIdx.x;
    int j0 = t*2, j1 = t*2+1;
    float gate0 = g_gates[j0], gate1 = g_gates[j1];
    int e0 = g_ape[j0], e1 = g_ape[j1];
    int p0 = g_posmap[j0], p1 = g_posmap[j1];
    const size_t yst = (size_t)NA*DIM;
    float s = 0.f;
    #pragma unroll
    for (int j = 0; j < 3; j++){
        int d = tid + 128*j;
        float y0 = 0.f, y1 = 0.f;
        #pragma unroll
        for (int z = 0; z < MOE2SK; z++){
            y0 += g_y[z*yst + (size_t)p0*DIM + d];
            y1 += g_y[z*yst + (size_t)p1*DIM + d];
        }
        float m0 = y0 - bias0[e0*DIM + d] + g_biassum[d];
        float m1 = y1 - bias0[e1*DIM + d] + g_biassum[DIM + d];
        float v = g_t[(size_t)t*DIM + d] + gate0*m0 + gate1*m1;
        buf[d] = v; s += v;
    }
    float mean = blk_sum(s, red) * (1.0f/DIM);
    float vs = 0.f;
    #pragma unroll
    for (int j = 0; j < 3; j++){ float d = buf[tid+128*j] - mean; vs += d*d; }
    float var = blk_sum(vs, red) * (1.0f/DIM);
    float inv = rsqrtf(var + 1e-5f);
    #pragma unroll
    for (int j = 0; j < 3; j++){
        int d = tid + 128*j;
        float y = (buf[d] - mean) * inv * gw[d] + bw[d];
        g_t[(size_t)t*DIM + d] = y;
        float2 pr = tf32_pair(y);
        g_th[(size_t)t*DIM + d] = pr.x;
        g_tl[(size_t)t*DIM + d] = pr.y;
    }
}

// ---------------- final LN + classifier ----------------
__global__ void final_ln_k(const float* __restrict__ gw, const float* __restrict__ bw){
    int b = blockIdx.x;
    int row = b * SEQ;
    __shared__ float buf[DIM];
    __shared__ float red[32];
    int tid = threadIdx.x;
    float s = 0.f;
    for (int i = tid; i < DIM; i += blockDim.x){
        float v = g_t[(size_t)row*DIM + i];
        buf[i] = v; s += v;
    }
    float mean = blk_sum(s, red) * (1.0f/DIM);
    float vs = 0.f;
    for (int i = tid; i < DIM; i += blockDim.x){ float d = buf[i] - mean; vs += d*d; }
    float var = blk_sum(vs, red) * (1.0f/DIM);
    float inv = rsqrtf(var + 1e-5f);
    for (int i = tid; i < DIM; i += blockDim.x)
        g_cls[b*DIM + i] = (buf[i] - mean) * inv * gw[i] + bw[i];
}

__global__ void classifier_k(const float* __restrict__ fcw, const float* __restrict__ fcb,
                             float* __restrict__ out){
    int b = blockIdx.x;
    int c = blockIdx.y * 128 + threadIdx.x;
    if (c >= NCLS) return;
    float acc = fcb[c];
    const float* xr = g_cls + b*DIM;
    for (int d = 0; d < DIM; d++) acc += xr[d] * fcw[(size_t)d*NCLS + c];
    out[b*NCLS + c] = acc;
}

// ---------------- host orchestration ----------------
extern "C" void kernel_launch(void* const* d_in, const int* in_sizes, int n_in,
                              void* d_out, int out_size){
    const float* x        = (const float*)d_in[0];
    const float* patch_w  = (const float*)d_in[1];
    const float* patch_b  = (const float*)d_in[2];
    const float* cls_tok  = (const float*)d_in[3];
    const float* pos      = (const float*)d_in[4];
    const float* qkv_w    = (const float*)d_in[5];
    const float* qkv_b    = (const float*)d_in[6];
    const float* proj_w   = (const float*)d_in[7];
    const float* proj_b   = (const float*)d_in[8];
    const float* ln1_g    = (const float*)d_in[9];
    const float* ln1_b    = (const float*)d_in[10];
    const float* ln2_g    = (const float*)d_in[11];
    const float* ln2_b    = (const float*)d_in[12];
    const float* router_w = (const float*)d_in[13];
    const float* router_b = (const float*)d_in[14];
    const float* w1       = (const float*)d_in[15];
    const float* b1       = (const float*)d_in[16];
    const float* w2       = (const float*)d_in[17];
    const float* b2       = (const float*)d_in[18];
    const float* norm_g   = (const float*)d_in[19];
    const float* norm_b   = (const float*)d_in[20];
    const float* fc_w     = (const float*)d_in[21];
    const float* fc_b     = (const float*)d_in[22];
    float* out            = (float*)d_out;

    float *p_a, *p_patches, *p_noise, *p_bias0;
    cudaGetSymbolAddress((void**)&p_a,       g_a);
    cudaGetSymbolAddress((void**)&p_patches, g_patches);
    cudaGetSymbolAddress((void**)&p_noise,   g_noise);
    cudaGetSymbolAddress((void**)&p_bias0,   g_bias0);

    cudaFuncSetAttribute(moe1_mma, cudaFuncAttributeMaxDynamicSharedMemorySize, MMA_SMEM);
    cudaFuncSetAttribute(moe2_mma, cudaFuncAttributeMaxDynamicSharedMemorySize, MMA_SMEM);
    cudaFuncSetAttribute(qkv_mma,  cudaFuncAttributeMaxDynamicSharedMemorySize, MMA_SMEM);
    cudaFuncSetAttribute(proj_mma, cudaFuncAttributeMaxDynamicSharedMemorySize, MMA_SMEM);

    noise_k<<<dim3((NOISE_N+255)/256, NL), 256>>>();
    bias0_all_k<<<dim3(NE, DIM/128, NL), 128>>>(b1, w2, b2);

    patchify_k<<<(NB*NPAT*PFD + 255)/256, 256>>>(x);
    sgemm64sk<<<dim3((NB*NPAT+63)/64, DIM/64, 4), 256>>>(p_patches, patch_w, patch_b, p_a,
                                                         NB*NPAT, DIM, PFD, PFD/4);
    assemble_k<<<(NT*DIM + 255)/256, 256>>>(cls_tok, pos);

    for (int l = 0; l < NL; l++){
        qkv_mma<<<dim3((NT+127)/128, QKVD/128, QKVSK), 256, MMA_SMEM>>>(
            qkv_w + (size_t)l*DIM*QKVD, qkv_b + l*QKVD);
        attn_fused_k<<<dim3((SEQ+31)/32, NB*NHD), 256>>>();
        proj_mma<<<dim3((NT+127)/128, DIM/128, PROJSK), 256, MMA_SMEM>>>(
            proj_w + (size_t)l*DIM*DIM, proj_b + l*DIM);
        add_ln_router_k<<<NT, 128>>>(ln1_g + l*DIM, ln1_b + l*DIM,
                                     router_w + (size_t)l*DIM*NE, router_b + l*NE,
                                     p_noise + (size_t)l*NOISE_N);
        route_k<<<1, 1024>>>(p_bias0 + (size_t)l*NE*DIM);

        moe1_mma<<<dim3((NA+127)/128, HID/128, NE), 256, MMA_SMEM>>>(
            w1 + (size_t)l*NE*DIM*HID, b1 + (size_t)l*NE*HID);
        moe2_mma<<<dim3((NA+127)/128, DIM/128, NE*MOE2SK), 256, MMA_SMEM>>>(
            w2 + (size_t)l*NE*HID*DIM, b2 + (size_t)l*NE*DIM);
        combine_ln_k<<<NT, 128>>>(p_bias0 + (size_t)l*NE*DIM,
                                  ln2_g + l*DIM, ln2_b + l*DIM);
    }

    final_ln_k<<<NB, 128>>>(norm_g, norm_b);
    classifier_k<<<dim3(NB, (NCLS+127)/128), 128>>>(fc_w, fc_b, out);
}

// round 17
// speedup vs baseline: 1.0184x; 1.0184x over previous
#include <cuda_runtime.h>
#include <math.h>
#include <stdint.h>

// ---------------- problem constants ----------------
#define NL    4
#define DIM   384
#define HID   1536
#define NHD   6
#define HDM   64
#define NE    8
#define NTOP  2
#define SEQ   197
#define NB    8
#define NT    (NB*SEQ)     // 1576
#define NA    (NT*NTOP)    // 3152
#define NCLS  1000
#define NPAT  196
#define PFD   768
#define QKVD  (3*DIM)      // 1152
#define NOISE_N (NT*NE)
#define MOE2SK 4
#define QKVSK  2

// ---------------- scratch ----------------
__device__ __align__(16) float g_t[NT*DIM];
__device__ __align__(16) float g_th[NT*DIM];
__device__ __align__(16) float g_tl[NT*DIM];
__device__ __align__(16) float g_qp[QKVSK*NT*QKVD];
__device__ __align__(16) float g_o[NT*DIM];
__device__ __align__(16) float g_a[4*NT*DIM];
__device__ __align__(16) float g_patches[NB*NPAT*PFD];
__device__ float g_noise[NL*NOISE_N];
__device__ float g_logits[NT*NE];
__device__ int   g_ape[NA];
__device__ int   g_appos[NA];
__device__ float g_gates[NA];
__device__ int   g_cnt[NE];
__device__ int   g_off[NE+1];
__device__ int   g_list[NA];
__device__ int   g_posmap[NA];
__device__ __align__(16) float g_hh[NA*HID];
__device__ __align__(16) float g_hl[NA*HID];
__device__ __align__(16) float g_y[MOE2SK*NA*DIM];
__device__ float g_bias0[NL*NE*DIM];
__device__ float g_biassum[NTOP*DIM];
__device__ float g_cls[NB*DIM];

// ---------------- f32x2 packed helpers (scalar GEMM path) ----------------
__device__ __forceinline__ unsigned long long dup2(float b){
    unsigned long long r;
    asm("mov.b64 %0, {%1, %1};" : "=l"(r) : "r"(__float_as_uint(b)));
    return r;
}
__device__ __forceinline__ void ffma2(unsigned long long& acc,
                                      unsigned long long a, unsigned long long b){
    asm("fma.rn.f32x2 %0, %1, %2, %0;" : "+l"(acc) : "l"(a), "l"(b));
}
__device__ __forceinline__ float2 unpk(unsigned long long v){
    unsigned lo, hi;
    asm("mov.b64 {%0, %1}, %2;" : "=r"(lo), "=r"(hi) : "l"(v));
    return make_float2(__uint_as_float(lo), __uint_as_float(hi));
}

// ---------------- misc helpers ----------------
__device__ __forceinline__ float blk_sum(float v, float* s32){
    int lane = threadIdx.x & 31, w = threadIdx.x >> 5;
    #pragma unroll
    for (int o = 16; o; o >>= 1) v += __shfl_xor_sync(0xffffffffu, v, o);
    if (lane == 0) s32[w] = v;
    __syncthreads();
    int nw = blockDim.x >> 5;
    float r = (threadIdx.x < nw) ? s32[threadIdx.x] : 0.f;
    #pragma unroll
    for (int o = 16; o; o >>= 1) r += __shfl_xor_sync(0xffffffffu, r, o);
    if (threadIdx.x == 0) s32[0] = r;
    __syncthreads();
    r = s32[0];
    __syncthreads();
    return r;
}

__device__ __forceinline__ float gelu_exact(float v){
    return 0.5f * v * (1.0f + erff(v * 0.70710678118654752f));
}

__device__ __forceinline__ float2 tf32_pair(float a){
    uint32_t h;
    asm("cvt.rna.tf32.f32 %0, %1;" : "=r"(h) : "f"(a));
    float hf = __uint_as_float(h);
    float l = a - hf;
    uint32_t lb;
    asm("cvt.rna.tf32.f32 %0, %1;" : "=r"(lb) : "f"(l));
    return make_float2(hf, __uint_as_float(lb));
}

// ---------------- JAX threefry ----------------
__device__ __forceinline__ void threefry(unsigned k0, unsigned k1,
                                         unsigned& x0, unsigned& x1){
    unsigned ks2 = k0 ^ k1 ^ 0x1BD11BDAu;
    x0 += k0; x1 += k1;
#define TF_RND(r) { x0 += x1; x1 = (x1 << r) | (x1 >> (32 - r)); x1 ^= x0; }
    TF_RND(13) TF_RND(15) TF_RND(26) TF_RND(6)
    x0 += k1;  x1 += ks2 + 1u;
    TF_RND(17) TF_RND(29) TF_RND(16) TF_RND(24)
    x0 += ks2; x1 += k0 + 2u;
    TF_RND(13) TF_RND(15) TF_RND(26) TF_RND(6)
    x0 += k0;  x1 += k1 + 3u;
    TF_RND(17) TF_RND(29) TF_RND(16) TF_RND(24)
    x0 += k1;  x1 += ks2 + 4u;
    TF_RND(13) TF_RND(15) TF_RND(26) TF_RND(6)
    x0 += ks2; x1 += k0 + 5u;
#undef TF_RND
}

__device__ __forceinline__ float bits_to_normal(unsigned b){
    float f = __uint_as_float((b >> 9) | 0x3f800000u) - 1.0f;
    const float lo = -0.99999994f;
    float u = f * 2.0f + lo;
    u = fmaxf(lo, u);
    return 1.4142135623730951f * erfinvf(u);
}

__global__ void noise_k(){
    int l = blockIdx.y;
    int i = blockIdx.x * blockDim.x + threadIdx.x;
    if (i >= NOISE_N) return;
    unsigned kk0 = 0u, kk1 = (unsigned)l;
    threefry(0u, 42u, kk0, kk1);
    unsigned x0 = 0u, x1 = (unsigned)i;
    threefry(kk0, kk1, x0, x1);
    g_noise[l*NOISE_N + i] = bits_to_normal(x0 ^ x1);
}

// ---------------- patchify / assemble ----------------
__global__ void patchify_k(const float* __restrict__ x){
    int idx = blockIdx.x * blockDim.x + threadIdx.x;
    if (idx >= NB*NPAT*PFD) return;
    int f = idx % PFD;
    int r = idx / PFD;
    int n = r % NPAT;
    int b = r / NPAT;
    int c  = f >> 8;
    int rem = f & 255;
    int py = rem >> 4, px = rem & 15;
    int ph = n / 14, pw = n % 14;
    g_patches[idx] = x[ ((size_t)(b*3 + c)*224 + (ph*16 + py))*224 + (pw*16 + px) ];
}

__global__ void assemble_k(const float* __restrict__ cls, const float* __restrict__ pos){
    int idx = blockIdx.x * blockDim.x + threadIdx.x;
    if (idx >= NT*DIM) return;
    int d = idx % DIM;
    int ts = idx / DIM;
    int s = ts % SEQ, b = ts / SEQ;
    float v;
    if (s == 0) v = cls[d];
    else {
        size_t p = (size_t)(b*NPAT + (s-1))*DIM + d;
        const size_t st = (size_t)NB*NPAT*DIM;
        v = g_a[p] + g_a[st + p] + g_a[2*st + p] + g_a[3*st + p];
    }
    float y = v + pos[s*DIM + d];
    g_t[idx] = y;
    float2 pr = tf32_pair(y);
    g_th[idx] = pr.x;
    g_tl[idx] = pr.y;
}

// =================== scalar f32x2 64x64 split-K GEMM (proj/patch) ==========
#define GEMM2(BM, R, LH, A_LOAD_EXPR, KDIM)                                   \
    __shared__ float As[2][16][(BM)+4];                                       \
    __shared__ float Bs[2][16][68];                                           \
    int tx = tid & 15, ty = tid >> 4;                                         \
    int am = tid >> 2, ak = (tid & 3) << 2;                                   \
    int bk = tid >> 4, bn = (tid & 15) << 2;                                  \
    unsigned long long acc2[(R)/2][4];                                        \
    _Pragma("unroll") for (int i = 0; i < (R)/2; i++)                         \
      _Pragma("unroll") for (int j = 0; j < 4; j++) acc2[i][j] = 0ull;        \
    float4 ra[LH], rb;                                                        \
    {   int k0 = 0;                                                           \
        _Pragma("unroll") for (int hh = 0; hh < (LH); hh++){                  \
            int m = am + hh*64; ra[hh] = A_LOAD_EXPR; }                       \
        rb = *(const float4*)&Bp[(size_t)bk*Nn + n0 + bn];                    \
    }                                                                         \
    _Pragma("unroll") for (int hh = 0; hh < (LH); hh++){                      \
        int m = am + hh*64;                                                   \
        As[0][ak+0][m]=ra[hh].x; As[0][ak+1][m]=ra[hh].y;                     \
        As[0][ak+2][m]=ra[hh].z; As[0][ak+3][m]=ra[hh].w; }                   \
    *(float4*)&Bs[0][bk][bn] = rb;                                            \
    __syncthreads();                                                          \
    const int nk = (KDIM)/16;                                                 \
    for (int kt = 0; kt < nk; kt++){                                          \
        int cur = kt & 1;                                                     \
        if (kt+1 < nk){                                                       \
            int k0 = (kt+1)*16;                                               \
            _Pragma("unroll") for (int hh = 0; hh < (LH); hh++){              \
                int m = am + hh*64; ra[hh] = A_LOAD_EXPR; }                   \
            rb = *(const float4*)&Bp[(size_t)(k0+bk)*Nn + n0 + bn];           \
        }                                                                     \
        _Pragma("unroll")                                                     \
        for (int kk = 0; kk < 16; kk++){                                      \
            float4 bv = *(float4*)&Bs[cur][kk][tx*4];                         \
            unsigned long long bd0=dup2(bv.x), bd1=dup2(bv.y),                \
                               bd2=dup2(bv.z), bd3=dup2(bv.w);                \
            _Pragma("unroll")                                                 \
            for (int ii = 0; ii < (R)/4; ii++){                               \
                ulonglong2 aa = *(const ulonglong2*)&As[cur][kk][ty*(R)+ii*4];\
                ffma2(acc2[ii*2+0][0], aa.x, bd0);                            \
                ffma2(acc2[ii*2+0][1], aa.x, bd1);                            \
                ffma2(acc2[ii*2+0][2], aa.x, bd2);                            \
                ffma2(acc2[ii*2+0][3], aa.x, bd3);                            \
                ffma2(acc2[ii*2+1][0], aa.y, bd0);                            \
                ffma2(acc2[ii*2+1][1], aa.y, bd1);                            \
                ffma2(acc2[ii*2+1][2], aa.y, bd2);                            \
                ffma2(acc2[ii*2+1][3], aa.y, bd3);                            \
            }                                                                 \
        }                                                                     \
        if (kt+1 < nk){                                                       \
            int nxt = 1 - cur;                                                \
            _Pragma("unroll") for (int hh = 0; hh < (LH); hh++){              \
                int m = am + hh*64;                                           \
                As[nxt][ak+0][m]=ra[hh].x; As[nxt][ak+1][m]=ra[hh].y;         \
                As[nxt][ak+2][m]=ra[hh].z; As[nxt][ak+3][m]=ra[hh].w; }       \
            *(float4*)&Bs[nxt][bk][bn] = rb;                                  \
        }                                                                     \
        __syncthreads();                                                      \
    }

__global__ void __launch_bounds__(256, 2)
sgemm64sk(const float* __restrict__ A, const float* __restrict__ Bp0,
          const float* __restrict__ bias, float* __restrict__ C,
          int M, int Nn, int K, int Kh){
    int tid = threadIdx.x;
    int z = blockIdx.z;
    int koff = z * Kh;
    const float* Bp = Bp0 + (size_t)koff * Nn;
    int m0 = blockIdx.x * 64, n0 = blockIdx.y * 64;
    GEMM2(64, 4, 1,
          (m0+m < M) ? *(const float4*)&A[(size_t)(m0+m)*K + koff + k0 + ak]
                     : make_float4(0,0,0,0), Kh)
    float4 bb = make_float4(0,0,0,0);
    if (z == 0) bb = *(const float4*)&bias[n0 + tx*4];
    float* Cz = C + (size_t)z*M*Nn;
    #pragma unroll
    for (int i2 = 0; i2 < 2; i2++){
        float2 u0=unpk(acc2[i2][0]), u1=unpk(acc2[i2][1]),
               u2=unpk(acc2[i2][2]), u3=unpk(acc2[i2][3]);
        int r = m0 + ty*4 + i2*2;
        if (r < M)
            *(float4*)&Cz[(size_t)r*Nn + n0 + tx*4] =
                make_float4(u0.x+bb.x, u1.x+bb.y, u2.x+bb.z, u3.x+bb.w);
        if (r+1 < M)
            *(float4*)&Cz[(size_t)(r+1)*Nn + n0 + tx*4] =
                make_float4(u0.y+bb.x, u1.y+bb.y, u2.y+bb.z, u3.y+bb.w);
    }
}

// =================== mma.sync TF32 (3xTF32) GEMM ===========================
#define MMA_SMEM ((2*8448 + 128)*4)

#define SA_H(b,k,m) sm[(b)*8448 + (k)*132 + (m)]
#define SA_L(b,k,m) sm[(b)*8448 + 2112 + (k)*132 + (m)]
#define SB_H(b,k,n) sm[(b)*8448 + 4224 + (k)*132 + (n)]
#define SB_L(b,k,n) sm[(b)*8448 + 6336 + (k)*132 + (n)]

#define MMA8(c, a, b)                                                         \
    asm volatile("mma.sync.aligned.m16n8k8.row.col.f32.tf32.tf32.f32 "        \
        "{%0,%1,%2,%3}, {%4,%5,%6,%7}, {%8,%9}, {%0,%1,%2,%3};"               \
        : "+f"((c)[0]), "+f"((c)[1]), "+f"((c)[2]), "+f"((c)[3])              \
        : "r"(__float_as_uint((a)[0])), "r"(__float_as_uint((a)[1])),         \
          "r"(__float_as_uint((a)[2])), "r"(__float_as_uint((a)[3])),         \
          "r"(__float_as_uint((b)[0])), "r"(__float_as_uint((b)[1])))

#define STAGE_STORE(b)                                                        \
    _Pragma("unroll") for (int i = 0; i < 2; i++){                            \
        int idx = tid + i*256; int m = idx >> 2; int kq = (idx & 3) << 2;     \
        SA_H(b,kq+0,m)=rah[i].x; SA_L(b,kq+0,m)=ral[i].x;                     \
        SA_H(b,kq+1,m)=rah[i].y; SA_L(b,kq+1,m)=ral[i].y;                     \
        SA_H(b,kq+2,m)=rah[i].z; SA_L(b,kq+2,m)=ral[i].z;                     \
        SA_H(b,kq+3,m)=rah[i].w; SA_L(b,kq+3,m)=ral[i].w;                     \
    }                                                                         \
    _Pragma("unroll") for (int i = 0; i < 2; i++){                            \
        int idx = tid + i*256; int r = idx >> 5; int c = (idx & 31) << 2;     \
        float2 q0 = tf32_pair(rbr[i].x), q1 = tf32_pair(rbr[i].y);            \
        float2 q2 = tf32_pair(rbr[i].z), q3 = tf32_pair(rbr[i].w);            \
        *(float4*)&SB_H(b,r,c) = make_float4(q0.x,q1.x,q2.x,q3.x);            \
        *(float4*)&SB_L(b,r,c) = make_float4(q0.y,q1.y,q2.y,q3.y);            \
    }

#define TF32_CORE(KDIM, A4H, A4L, B4)                                         \
    const int lane = tid & 31;                                                \
    const int warp_m = (tid >> 5) & 1, warp_n = tid >> 6;                     \
    const int g = lane >> 2, tig = lane & 3;                                  \
    float acc[4][4][4];                                                       \
    _Pragma("unroll") for (int i = 0; i < 4; i++)                             \
      _Pragma("unroll") for (int j = 0; j < 4; j++)                           \
        _Pragma("unroll") for (int q = 0; q < 4; q++) acc[i][j][q] = 0.f;     \
    float4 rah[2], ral[2], rbr[2];                                            \
    {                                                                         \
        _Pragma("unroll") for (int i = 0; i < 2; i++){                        \
            int idx = tid + i*256; int m = idx >> 2;                          \
            int kq = (idx & 3) << 2;                                          \
            rah[i] = A4H; ral[i] = A4L; }                                     \
        _Pragma("unroll") for (int i = 0; i < 2; i++){                        \
            int idx = tid + i*256; int r = idx >> 5;                          \
            int c = (idx & 31) << 2;                                          \
            rbr[i] = B4; }                                                    \
    }                                                                         \
    STAGE_STORE(0)                                                            \
    __syncthreads();                                                          \
    const int nk = (KDIM)/16;                                                 \
    for (int kt = 0; kt < nk; kt++){                                          \
        int cur = kt & 1;                                                     \
        if (kt+1 < nk){                                                       \
            int k0n = (kt+1)*16;                                              \
            _Pragma("unroll") for (int i = 0; i < 2; i++){                    \
                int idx = tid + i*256; int m = idx >> 2;                      \
                int kq = ((idx & 3) << 2) + k0n;                              \
                rah[i] = A4H; ral[i] = A4L; }                                 \
            _Pragma("unroll") for (int i = 0; i < 2; i++){                    \
                int idx = tid + i*256; int r = (idx >> 5) + k0n;              \
                int c = (idx & 31) << 2;                                      \
                rbr[i] = B4; }                                                \
        }                                                                     \
        _Pragma("unroll") for (int ks = 0; ks < 2; ks++){                     \
            float ah[4][4], al[4][4];                                         \
            _Pragma("unroll") for (int mt = 0; mt < 4; mt++){                 \
                int mi = warp_m*64 + mt*16 + g;                               \
                int kr = ks*8 + tig;                                          \
                ah[mt][0]=SA_H(cur,kr,mi);   ah[mt][1]=SA_H(cur,kr,mi+8);     \
                ah[mt][2]=SA_H(cur,kr+4,mi); ah[mt][3]=SA_H(cur,kr+4,mi+8);   \
                al[mt][0]=SA_L(cur,kr,mi);   al[mt][1]=SA_L(cur,kr,mi+8);     \
                al[mt][2]=SA_L(cur,kr+4,mi); al[mt][3]=SA_L(cur,kr+4,mi+8);   \
            }                                                                 \
            float bhf[4][2], blf[4][2];                                       \
            _Pragma("unroll") for (int nt = 0; nt < 4; nt++){                 \
                int ni = warp_n*32 + nt*8 + g;                                \
                int kr = ks*8 + tig;                                          \
                bhf[nt][0]=SB_H(cur,kr,ni); bhf[nt][1]=SB_H(cur,kr+4,ni);     \
                blf[nt][0]=SB_L(cur,kr,ni); blf[nt][1]=SB_L(cur,kr+4,ni);     \
            }                                                                 \
            _Pragma("unroll") for (int mt = 0; mt < 4; mt++)                  \
                _Pragma("unroll") for (int nt = 0; nt < 4; nt++){             \
                    MMA8(acc[mt][nt], ah[mt], bhf[nt]);                       \
                    MMA8(acc[mt][nt], ah[mt], blf[nt]);                       \
                    MMA8(acc[mt][nt], al[mt], bhf[nt]);                       \
                }                                                             \
        }                                                                     \
        if (kt+1 < nk){ STAGE_STORE(1 - cur) }                                \
        __syncthreads();                                                      \
    }

// ---- MoE FFN1 ----
__global__ void __launch_bounds__(256)
moe1_mma(const float* __restrict__ w1, const float* __restrict__ b1){
    int e = blockIdx.z;
    int cnt = g_cnt[e];
    int m0 = blockIdx.x * 128;
    if (m0 >= cnt) return;
    int off = g_off[e];
    extern __shared__ float sm[];
    int* rows = (int*)(sm + 2*8448);
    int tid = threadIdx.x;
    if (tid < 128) rows[tid] = (m0 + tid < cnt) ? (g_list[off + m0 + tid] >> 1) : 0;
    __syncthreads();
    int n0 = blockIdx.y * 128;
    const float* Bw = w1 + (size_t)e*DIM*HID;
    TF32_CORE(DIM,
        (*(const float4*)&g_th[(size_t)rows[m]*DIM + kq]),
        (*(const float4*)&g_tl[(size_t)rows[m]*DIM + kq]),
        (*(const float4*)&Bw[(size_t)r*HID + n0 + c]))
    #pragma unroll
    for (int mt = 0; mt < 4; mt++){
        #pragma unroll
        for (int nt = 0; nt < 4; nt++){
            int lr = warp_m*64 + mt*16 + g;
            int col = n0 + warp_n*32 + nt*8 + tig*2;
            float b0v = b1[e*HID + col], b1v = b1[e*HID + col + 1];
            int r1 = m0 + lr;
            if (r1 < cnt){
                float v0 = gelu_exact(acc[mt][nt][0]+b0v);
                float v1 = gelu_exact(acc[mt][nt][1]+b1v);
                float2 s0 = tf32_pair(v0), s1 = tf32_pair(v1);
                size_t p = (size_t)(off+r1)*HID + col;
                *(float2*)&g_hh[p] = make_float2(s0.x, s1.x);
                *(float2*)&g_hl[p] = make_float2(s0.y, s1.y);
            }
            int r2 = r1 + 8;
            if (r2 < cnt){
                float v0 = gelu_exact(acc[mt][nt][2]+b0v);
                float v1 = gelu_exact(acc[mt][nt][3]+b1v);
                float2 s0 = tf32_pair(v0), s1 = tf32_pair(v1);
                size_t p = (size_t)(off+r2)*HID + col;
                *(float2*)&g_hh[p] = make_float2(s0.x, s1.x);
                *(float2*)&g_hl[p] = make_float2(s0.y, s1.y);
            }
        }
    }
}

// ---- MoE FFN2 (split-K=MOE2SK) ----
__global__ void __launch_bounds__(256)
moe2_mma(const float* __restrict__ w2, const float* __restrict__ b2){
    int ez = blockIdx.z;
    int e = ez / MOE2SK, zk = ez % MOE2SK;
    int cnt = g_cnt[e];
    int m0 = blockIdx.x * 128;
    if (m0 >= cnt) return;
    int off = g_off[e];
    extern __shared__ float sm[];
    int tid = threadIdx.x;
    int n0 = blockIdx.y * 128;
    const int KH = HID / MOE2SK;
    int koff = zk * KH;
    const float* Bw = w2 + (size_t)e*HID*DIM;
    TF32_CORE(KH,
        (*(const float4*)&g_hh[(size_t)(off + ((m0+m < cnt) ? (m0+m) : (cnt-1)))*HID + koff + kq]),
        (*(const float4*)&g_hl[(size_t)(off + ((m0+m < cnt) ? (m0+m) : (cnt-1)))*HID + koff + kq]),
        (*(const float4*)&Bw[(size_t)(koff + r)*DIM + n0 + c]))
    float* Y = g_y + (size_t)zk*NA*DIM;
    #pragma unroll
    for (int mt = 0; mt < 4; mt++){
        #pragma unroll
        for (int nt = 0; nt < 4; nt++){
            int lr = warp_m*64 + mt*16 + g;
            int col = n0 + warp_n*32 + nt*8 + tig*2;
            float b0v = 0.f, b1v = 0.f;
            if (zk == 0){ b0v = b2[e*DIM + col]; b1v = b2[e*DIM + col + 1]; }
            int r1 = m0 + lr;
            if (r1 < cnt)
                *(float2*)&Y[(size_t)(off+r1)*DIM + col] =
                    make_float2(acc[mt][nt][0]+b0v, acc[mt][nt][1]+b1v);
            int r2 = r1 + 8;
            if (r2 < cnt)
                *(float2*)&Y[(size_t)(off+r2)*DIM + col] =
                    make_float2(acc[mt][nt][2]+b0v, acc[mt][nt][3]+b1v);
        }
    }
}

// ---- QKV (split-K=QKVSK; partials consumed directly by attention) ----
__global__ void __launch_bounds__(256)
qkv_mma(const float* __restrict__ wq, const float* __restrict__ bq){
    int m0 = blockIdx.x * 128;
    int zk = blockIdx.z;
    extern __shared__ float sm[];
    int tid = threadIdx.x;
    int n0 = blockIdx.y * 128;
    const int KH = DIM / QKVSK;
    int koff = zk * KH;
    TF32_CORE(KH,
        (*(const float4*)&g_th[(size_t)((m0+m < NT) ? (m0+m) : (NT-1))*DIM + koff + kq]),
        (*(const float4*)&g_tl[(size_t)((m0+m < NT) ? (m0+m) : (NT-1))*DIM + koff + kq]),
        (*(const float4*)&wq[(size_t)(koff + r)*QKVD + n0 + c]))
    float* P = g_qp + (size_t)zk*NT*QKVD;
    #pragma unroll
    for (int mt = 0; mt < 4; mt++){
        #pragma unroll
        for (int nt = 0; nt < 4; nt++){
            int lr = warp_m*64 + mt*16 + g;
            int col = n0 + warp_n*32 + nt*8 + tig*2;
            float b0v = 0.f, b1v = 0.f;
            if (zk == 0){ b0v = bq[col]; b1v = bq[col + 1]; }
            int r1 = m0 + lr;
            if (r1 < NT)
                *(float2*)&P[(size_t)r1*QKVD + col] =
                    make_float2(acc[mt][nt][0]+b0v, acc[mt][nt][1]+b1v);
            int r2 = r1 + 8;
            if (r2 < NT)
                *(float2*)&P[(size_t)r2*QKVD + col] =
                    make_float2(acc[mt][nt][2]+b0v, acc[mt][nt][3]+b1v);
        }
    }
}

// ---------------- fused attention (sums qkv split-K partials inline) -------
__global__ void attn_fused_k(){
    int bh = blockIdx.y; int b = bh / NHD, h = bh % NHD;
    int q0 = blockIdx.x * 32;
    __shared__ float Qs[32][68];
    __shared__ float KVs[32][68];
    __shared__ float Ss[32][224];
    int tid = threadIdx.x;
    const size_t qst = (size_t)NT*QKVD;
    #pragma unroll
    for (int li = 0; li < 2; li++){
        int idx = tid + li*256;
        int r = idx >> 4, c = (idx & 15) << 2;
        int q = q0 + r;
        float4 v = make_float4(0,0,0,0);
        if (q < SEQ){
            size_t p = (size_t)(b*SEQ+q)*QKVD + h*HDM + c;
            float4 v0 = *(const float4*)&g_qp[p];
            float4 v1 = *(const float4*)&g_qp[qst + p];
            v = make_float4(v0.x+v1.x, v0.y+v1.y, v0.z+v1.z, v0.w+v1.w);
        }
        *(float4*)&Qs[r][c] = v;
    }
    int tx = tid & 15, ty = tid >> 4;
    for (int k0 = 0; k0 < 224; k0 += 32){
        #pragma unroll
        for (int li = 0; li < 2; li++){
            int idx = tid + li*256;
            int r = idx >> 4, c = (idx & 15) << 2;
            int k = k0 + r;
            float4 w = make_float4(0,0,0,0);
            if (k < SEQ){
                size_t p = (size_t)(b*SEQ+k)*QKVD + DIM + h*HDM + c;
                float4 v0 = *(const float4*)&g_qp[p];
                float4 v1 = *(const float4*)&g_qp[qst + p];
                w = make_float4(v0.x+v1.x, v0.y+v1.y, v0.z+v1.z, v0.w+v1.w);
            }
            *(float4*)&KVs[r][c] = w;
        }
        __syncthreads();
        float acc[2][2] = {};
        #pragma unroll
        for (int d = 0; d < HDM; d++){
            float a0 = Qs[ty*2][d],   a1 = Qs[ty*2+1][d];
            float b0 = KVs[tx*2][d],  b1 = KVs[tx*2+1][d];
            acc[0][0] += a0*b0; acc[0][1] += a0*b1;
            acc[1][0] += a1*b0; acc[1][1] += a1*b1;
        }
        #pragma unroll
        for (int i = 0; i < 2; i++){
            #pragma unroll
            for (int j = 0; j < 2; j++){
                int k = k0 + tx*2 + j;
                Ss[ty*2+i][k] = (k < SEQ) ? acc[i][j]*0.125f : -1.0e30f;
            }
        }
        __syncthreads();
    }
    int lane = tid & 31, w = tid >> 5;
    #pragma unroll
    for (int rr = 0; rr < 4; rr++){
        int row = w*4 + rr;
        float m = -3.0e38f;
        for (int i = lane; i < SEQ; i += 32) m = fmaxf(m, Ss[row][i]);
        #pragma unroll
        for (int o = 16; o; o >>= 1) m = fmaxf(m, __shfl_xor_sync(0xffffffffu, m, o));
        float s = 0.f;
        for (int i = lane; i < SEQ; i += 32){
            float e = expf(Ss[row][i] - m);
            Ss[row][i] = e; s += e;
        }
        #pragma unroll
        for (int o = 16; o; o >>= 1) s += __shfl_xor_sync(0xffffffffu, s, o);
        float inv = 1.0f / s;
        for (int i = lane; i < 224; i += 32)
            Ss[row][i] = (i < SEQ) ? Ss[row][i]*inv : 0.f;
    }
    __syncthreads();
    // AV: each thread owns rows (vr + 8i, i<4) x cols (vc, vc+1)
    int vc = (tid & 31) << 1;
    int vr = tid >> 5;
    float accv[4][2] = {};
    for (int k0 = 0; k0 < 224; k0 += 32){
        #pragma unroll
        for (int li = 0; li < 2; li++){
            int idx = tid + li*256;
            int r = idx >> 4, c = (idx & 15) << 2;
            int k = k0 + r;
            float4 v = make_float4(0,0,0,0);
            if (k < SEQ){
                size_t p = (size_t)(b*SEQ+k)*QKVD + 2*DIM + h*HDM + c;
                float4 v0 = *(const float4*)&g_qp[p];
                float4 v1 = *(const float4*)&g_qp[qst + p];
                v = make_float4(v0.x+v1.x, v0.y+v1.y, v0.z+v1.z, v0.w+v1.w);
            }
            *(float4*)&KVs[r][c] = v;
        }
        __syncthreads();
        #pragma unroll
        for (int kk = 0; kk < 32; kk++){
            float2 vv = *(float2*)&KVs[kk][vc];
            #pragma unroll
            for (int i = 0; i < 4; i++){
                float s = Ss[vr + 8*i][k0+kk];
                accv[i][0] += s*vv.x;
                accv[i][1] += s*vv.y;
            }
        }
        __syncthreads();
    }
    #pragma unroll
    for (int i = 0; i < 4; i++){
        int q = q0 + vr + 8*i;
        if (q < SEQ)
            *(float2*)&g_o[(size_t)(b*SEQ+q)*DIM + h*HDM + vc] =
                make_float2(accv[i][0], accv[i][1]);
    }
}

// ---------------- fused: residual add + LN1 + router (+ split emit) --------
__global__ void add_ln_router_k(const float* __restrict__ gw, const float* __restrict__ bw,
                                const float* __restrict__ rw, const float* __restrict__ rb,
                                const float* __restrict__ noise){
    int t = blockIdx.x;
    __shared__ float buf[DIM];
    __shared__ float red[32];
    __shared__ float s_part[4][NE];
    int tid = threadIdx.x;
    float s = 0.f;
    const size_t st = (size_t)NT*DIM;
    #pragma unroll
    for (int j = 0; j < 3; j++){
        int i = tid + 128*j;
        size_t p = (size_t)t*DIM + i;
        float v = g_t[p] + g_a[p] + g_a[st + p] + g_a[2*st + p] + g_a[3*st + p];
        buf[i] = v; s += v;
    }
    float mean = blk_sum(s, red) * (1.0f/DIM);
    float vs = 0.f;
    #pragma unroll
    for (int j = 0; j < 3; j++){ float d = buf[tid+128*j] - mean; vs += d*d; }
    float var = blk_sum(vs, red) * (1.0f/DIM);
    float inv = rsqrtf(var + 1e-5f);
    float acc[NE] = {};
    #pragma unroll
    for (int j = 0; j < 3; j++){
        int i = tid + 128*j;
        float y = (buf[i] - mean) * inv * gw[i] + bw[i];
        g_t[(size_t)t*DIM + i] = y;
        float2 pr = tf32_pair(y);
        g_th[(size_t)t*DIM + i] = pr.x;
        g_tl[(size_t)t*DIM + i] = pr.y;
        float4 r0 = *(const float4*)&rw[i*NE];
        float4 r1 = *(const float4*)&rw[i*NE + 4];
        acc[0] += y*r0.x; acc[1] += y*r0.y; acc[2] += y*r0.z; acc[3] += y*r0.w;
        acc[4] += y*r1.x; acc[5] += y*r1.y; acc[6] += y*r1.z; acc[7] += y*r1.w;
    }
    int lane = tid & 31, w = tid >> 5;
    #pragma unroll
    for (int e = 0; e < NE; e++){
        float v = acc[e];
        #pragma unroll
        for (int o = 16; o; o >>= 1) v += __shfl_xor_sync(0xffffffffu, v, o);
        if (lane == 0) s_part[w][e] = v;
    }
    __syncthreads();
    if (tid < NE){
        float v = s_part[0][tid] + s_part[1][tid] + s_part[2][tid] + s_part[3][tid];
        g_logits[t*NE + tid] = v + rb[tid] + 0.01f * noise[t*NE + tid];
    }
}

// ---------------- routing ----------------
__global__ void route_k(const float* __restrict__ bias0){
    __shared__ int s_cnt[NE];
    __shared__ int s_off[NE];
    __shared__ int s_occ[NTOP*NE];
    int tid = threadIdx.x;
    if (tid < NE) s_cnt[tid] = 0;
    if (tid < NTOP*NE) s_occ[tid] = 0;
    __syncthreads();
    for (int t = tid; t < NT; t += 1024){
        float v[NE];
        #pragma unroll
        for (int e = 0; e < NE; e++) v[e] = g_logits[t*NE + e];
        int i0 = 0; float v0 = v[0];
        #pragma unroll
        for (int e = 1; e < NE; e++) if (v[e] > v0){ v0 = v[e]; i0 = e; }
        int i1 = (i0 == 0) ? 1 : 0; float v1 = v[i1];
        #pragma unroll
        for (int e = 0; e < NE; e++) if (e != i0 && v[e] > v1){ v1 = v[e]; i1 = e; }
        float e1 = expf(v1 - v0);
        float inv = 1.0f / (1.0f + e1);
        g_gates[t*2]   = inv;
        g_gates[t*2+1] = e1 * inv;
        g_ape[t*2]   = i0;
        g_ape[t*2+1] = i1;
        g_appos[t*2]   = atomicAdd(&s_cnt[i0], 1);
        g_appos[t*2+1] = atomicAdd(&s_cnt[i1], 1);
        s_occ[i0] = 1;
        s_occ[NE + i1] = 1;
    }
    __syncthreads();
    if (tid == 0){
        int o = 0;
        for (int e = 0; e < NE; e++){
            s_off[e] = o; g_off[e] = o; g_cnt[e] = s_cnt[e]; o += s_cnt[e];
        }
        g_off[NE] = o;
    }
    __syncthreads();
    for (int j = tid; j < NA; j += 1024){
        int e = g_ape[j];
        int pos = s_off[e] + g_appos[j];
        g_list[pos] = j;
        g_posmap[j] = pos;
    }
    if (tid < NTOP*DIM){
        int k = tid / DIM, d = tid % DIM;
        float s = 0.f;
        #pragma unroll
        for (int e = 0; e < NE; e++)
            if (s_occ[k*NE + e]) s += bias0[e*DIM + d];
        g_biassum[k*DIM + d] = s;
    }
}

__global__ void bias0_all_k(const float* __restrict__ b1, const float* __restrict__ w2,
                            const float* __restrict__ b2){
    int l = blockIdx.z;
    int e = blockIdx.x;
    __shared__ float gb[HID];
    int tid = threadIdx.x;
    const float* b1l = b1 + ((size_t)l*NE + e)*HID;
    for (int h = tid; h < HID; h += 128) gb[h] = gelu_exact(b1l[h]);
    __syncthreads();
    int d = blockIdx.y * 128 + tid;
    const float* w = w2 + ((size_t)l*NE + e)*HID*DIM + d;
    float acc = b2[((size_t)l*NE + e)*DIM + d];
    for (int h = 0; h < HID; h++)
        acc += gb[h] * w[(size_t)h*DIM];
    g_bias0[((size_t)l*NE + e)*DIM + d] = acc;
}

// ---------------- fused: MoE combine (partials) + residual + LN2 -----------
__global__ void combine_ln_k(const float* __restrict__ bias0,
                             const float* __restrict__ gw, const float* __restrict__ bw){
    int t = blockIdx.x;
    __shared__ float buf[DIM];
    __shared__ float red[32];
    int tid = threadIdx.x;
    int j0 = t*2, j1 = t*2+1;
    float gate0 = g_gates[j0], gate1 = g_gates[j1];
    int e0 = g_ape[j0], e1 = g_ape[j1];
    int p0 = g_posmap[j0], p1 = g_posmap[j1];
    const size_t yst = (size_t)NA*DIM;
    float s = 0.f;
    #pragma unroll
    for (int j = 0; j < 3; j++){
        int d = tid + 128*j;
        float y0 = 0.f, y1 = 0.f;
        #pragma unroll
        for (int z = 0; z < MOE2SK; z++){
            y0 += g_y[z*yst + (size_t)p0*DIM + d];
            y1 += g_y[z*yst + (size_t)p1*DIM + d];
        }
        float m0 = y0 - bias0[e0*DIM + d] + g_biassum[d];
        float m1 = y1 - bias0[e1*DIM + d] + g_biassum[DIM + d];
        float v = g_t[(size_t)t*DIM + d] + gate0*m0 + gate1*m1;
        buf[d] = v; s += v;
    }
    float mean = blk_sum(s, red) * (1.0f/DIM);
    float vs = 0.f;
    #pragma unroll
    for (int j = 0; j < 3; j++){ float d = buf[tid+128*j] - mean; vs += d*d; }
    float var = blk_sum(vs, red) * (1.0f/DIM);
    float inv = rsqrtf(var + 1e-5f);
    #pragma unroll
    for (int j = 0; j < 3; j++){
        int d = tid + 128*j;
        float y = (buf[d] - mean) * inv * gw[d] + bw[d];
        g_t[(size_t)t*DIM + d] = y;
        float2 pr = tf32_pair(y);
        g_th[(size_t)t*DIM + d] = pr.x;
        g_tl[(size_t)t*DIM + d] = pr.y;
    }
}

// ---------------- final LN + classifier ----------------
__global__ void final_ln_k(const float* __restrict__ gw, const float* __restrict__ bw){
    int b = blockIdx.x;
    int row = b * SEQ;
    __shared__ float buf[DIM];
    __shared__ float red[32];
    int tid = threadIdx.x;
    float s = 0.f;
    for (int i = tid; i < DIM; i += blockDim.x){
        float v = g_t[(size_t)row*DIM + i];
        buf[i] = v; s += v;
    }
    float mean = blk_sum(s, red) * (1.0f/DIM);
    float vs = 0.f;
    for (int i = tid; i < DIM; i += blockDim.x){ float d = buf[i] - mean; vs += d*d; }
    float var = blk_sum(vs, red) * (1.0f/DIM);
    float inv = rsqrtf(var + 1e-5f);
    for (int i = tid; i < DIM; i += blockDim.x)
        g_cls[b*DIM + i] = (buf[i] - mean) * inv * gw[i] + bw[i];
}

__global__ void classifier_k(const float* __restrict__ fcw, const float* __restrict__ fcb,
                             float* __restrict__ out){
    int b = blockIdx.x;
    int c = blockIdx.y * 128 + threadIdx.x;
    if (c >= NCLS) return;
    float acc = fcb[c];
    const float* xr = g_cls + b*DIM;
    for (int d = 0; d < DIM; d++) acc += xr[d] * fcw[(size_t)d*NCLS + c];
    out[b*NCLS + c] = acc;
}

// ---------------- host orchestration ----------------
extern "C" void kernel_launch(void* const* d_in, const int* in_sizes, int n_in,
                              void* d_out, int out_size){
    const float* x        = (const float*)d_in[0];
    const float* patch_w  = (const float*)d_in[1];
    const float* patch_b  = (const float*)d_in[2];
    const float* cls_tok  = (const float*)d_in[3];
    const float* pos      = (const float*)d_in[4];
    const float* qkv_w    = (const float*)d_in[5];
    const float* qkv_b    = (const float*)d_in[6];
    const float* proj_w   = (const float*)d_in[7];
    const float* proj_b   = (const float*)d_in[8];
    const float* ln1_g    = (const float*)d_in[9];
    const float* ln1_b    = (const float*)d_in[10];
    const float* ln2_g    = (const float*)d_in[11];
    const float* ln2_b    = (const float*)d_in[12];
    const float* router_w = (const float*)d_in[13];
    const float* router_b = (const float*)d_in[14];
    const float* w1       = (const float*)d_in[15];
    const float* b1       = (const float*)d_in[16];
    const float* w2       = (const float*)d_in[17];
    const float* b2       = (const float*)d_in[18];
    const float* norm_g   = (const float*)d_in[19];
    const float* norm_b   = (const float*)d_in[20];
    const float* fc_w     = (const float*)d_in[21];
    const float* fc_b     = (const float*)d_in[22];
    float* out            = (float*)d_out;

    float *p_o, *p_a, *p_patches, *p_noise, *p_bias0;
    cudaGetSymbolAddress((void**)&p_o,       g_o);
    cudaGetSymbolAddress((void**)&p_a,       g_a);
    cudaGetSymbolAddress((void**)&p_patches, g_patches);
    cudaGetSymbolAddress((void**)&p_noise,   g_noise);
    cudaGetSymbolAddress((void**)&p_bias0,   g_bias0);

    cudaFuncSetAttribute(moe1_mma, cudaFuncAttributeMaxDynamicSharedMemorySize, MMA_SMEM);
    cudaFuncSetAttribute(moe2_mma, cudaFuncAttributeMaxDynamicSharedMemorySize, MMA_SMEM);
    cudaFuncSetAttribute(qkv_mma,  cudaFuncAttributeMaxDynamicSharedMemorySize, MMA_SMEM);

    noise_k<<<dim3((NOISE_N+255)/256, NL), 256>>>();
    bias0_all_k<<<dim3(NE, DIM/128, NL), 128>>>(b1, w2, b2);

    patchify_k<<<(NB*NPAT*PFD + 255)/256, 256>>>(x);
    sgemm64sk<<<dim3((NB*NPAT+63)/64, DIM/64, 4), 256>>>(p_patches, patch_w, patch_b, p_a,
                                                         NB*NPAT, DIM, PFD, PFD/4);
    assemble_k<<<(NT*DIM + 255)/256, 256>>>(cls_tok, pos);

    for (int l = 0; l < NL; l++){
        qkv_mma<<<dim3((NT+127)/128, QKVD/128, QKVSK), 256, MMA_SMEM>>>(
            qkv_w + (size_t)l*DIM*QKVD, qkv_b + l*QKVD);
        attn_fused_k<<<dim3((SEQ+31)/32, NB*NHD), 256>>>();
        sgemm64sk<<<dim3((NT+63)/64, DIM/64, 4), 256>>>(p_o, proj_w + (size_t)l*DIM*DIM,
                                                        proj_b + l*DIM, p_a, NT, DIM, DIM, DIM/4);
        add_ln_router_k<<<NT, 128>>>(ln1_g + l*DIM, ln1_b + l*DIM,
                                     router_w + (size_t)l*DIM*NE, router_b + l*NE,
                                     p_noise + (size_t)l*NOISE_N);
        route_k<<<1, 1024>>>(p_bias0 + (size_t)l*NE*DIM);

        moe1_mma<<<dim3((NA+127)/128, HID/128, NE), 256, MMA_SMEM>>>(
            w1 + (size_t)l*NE*DIM*HID, b1 + (size_t)l*NE*HID);
        moe2_mma<<<dim3((NA+127)/128, DIM/128, NE*MOE2SK), 256, MMA_SMEM>>>(
            w2 + (size_t)l*NE*HID*DIM, b2 + (size_t)l*NE*DIM);
        combine_ln_k<<<NT, 128>>>(p_bias0 + (size_t)l*NE*DIM,
                                  ln2_g + l*DIM, ln2_b + l*DIM);
    }

    final_ln_k<<<NB, 128>>>(norm_g, norm_b);
    classifier_k<<<dim3(NB, (NCLS+127)/128), 128>>>(fc_w, fc_b, out);
}